// round 7
// baseline (speedup 1.0000x reference)
#include <cuda_runtime.h>
#include <math.h>

#define N_NODES 100000
#define D 128

// Scratch: degrees [set][0=out(src)/1=in(dst)][node], Y = feats @ W  [N,128]
__device__ float g_deg[2][2][N_NODES];
__device__ float g_y[(size_t)N_NODES * D];

// ---------------- degree histograms (both sets) ----------------
__global__ void degree_kernel(const int* __restrict__ sp, const int* __restrict__ dp,
                              const int* __restrict__ sn, const int* __restrict__ dn, int E) {
    int i = blockIdx.x * blockDim.x + threadIdx.x;
    if (i >= E) return;
    atomicAdd(&g_deg[0][0][sp[i]], 1.0f);
    atomicAdd(&g_deg[0][1][dp[i]], 1.0f);
    atomicAdd(&g_deg[1][0][sn[i]], 1.0f);
    atomicAdd(&g_deg[1][1][dn[i]], 1.0f);
}

// ---------------- Y = feats @ W  (128x128 fp32 GEMM, 128-row tiles) ----------------
__global__ void ygemm_kernel(const float* __restrict__ feats, const float* __restrict__ W) {
    extern __shared__ float sm[];
    float* Ws = sm;            // [k][n]
    float* As = sm + D * D;    // [row][k]

    int tid = threadIdx.x;
    int row0 = blockIdx.x * D;

    {
        const float4* Wv = reinterpret_cast<const float4*>(W);
        float4* Wsv = reinterpret_cast<float4*>(Ws);
        #pragma unroll
        for (int i = tid; i < D * D / 4; i += 256) Wsv[i] = Wv[i];
    }
    {
        const float4* Av = reinterpret_cast<const float4*>(feats);
        float4* Asv = reinterpret_cast<float4*>(As);
        #pragma unroll
        for (int idx = tid; idx < D * (D / 4); idx += 256) {
            int row = idx >> 5;
            int c4  = idx & 31;
            int grow = row0 + row;
            float4 v = make_float4(0.f, 0.f, 0.f, 0.f);
            if (grow < N_NODES) v = Av[(size_t)grow * (D / 4) + c4];
            Asv[idx] = v;
        }
    }
    __syncthreads();

    int ty = tid >> 4;
    int tx = tid & 15;

    float acc[8][8];
    #pragma unroll
    for (int i = 0; i < 8; i++)
        #pragma unroll
        for (int j = 0; j < 8; j++) acc[i][j] = 0.0f;

    #pragma unroll 4
    for (int k = 0; k < D; k++) {
        float a[8];
        #pragma unroll
        for (int i = 0; i < 8; i++) a[i] = As[(ty * 8 + i) * D + k];
        float4 b0 = *reinterpret_cast<const float4*>(&Ws[k * D + tx * 8]);
        float4 b1 = *reinterpret_cast<const float4*>(&Ws[k * D + tx * 8 + 4]);
        float bb[8] = {b0.x, b0.y, b0.z, b0.w, b1.x, b1.y, b1.z, b1.w};
        #pragma unroll
        for (int i = 0; i < 8; i++)
            #pragma unroll
            for (int j = 0; j < 8; j++)
                acc[i][j] = fmaf(a[i], bb[j], acc[i][j]);
    }

    #pragma unroll
    for (int i = 0; i < 8; i++) {
        int grow = row0 + ty * 8 + i;
        if (grow >= N_NODES) continue;
        float4* o = reinterpret_cast<float4*>(&g_y[(size_t)grow * D + tx * 8]);
        o[0] = make_float4(acc[i][0], acc[i][1], acc[i][2], acc[i][3]);
        o[1] = make_float4(acc[i][4], acc[i][5], acc[i][6], acc[i][7]);
    }
}

// ---------------- merged edge scatter over both sets ----------------
// Global edge id eg in [0, 2E): set = eg / E, local edge e = eg % E.
// out[set][dst] += Y[src] * ns[set][src] * nd[set][dst]
// 4 edges per warp; all gathers issued before any RED.
__global__ void scatter2_kernel(const int* __restrict__ src_p, const int* __restrict__ dst_p,
                                const int* __restrict__ src_n, const int* __restrict__ dst_n,
                                int E, float* __restrict__ out) {
    int w = (blockIdx.x * blockDim.x + threadIdx.x) >> 5;
    int lane = threadIdx.x & 31;
    int eg0 = w * 4;
    int total = 2 * E;
    if (eg0 >= total) return;
    int n = total - eg0; if (n > 4) n = 4;

    const float4* Yv = reinterpret_cast<const float4*>(&g_y[0]);

    int s[4], d[4], st[4];
    #pragma unroll
    for (int i = 0; i < 4; i++) {
        int eg = eg0 + ((i < n) ? i : 0);
        int set = (eg >= E) ? 1 : 0;
        int e = eg - set * E;
        st[i] = set;
        s[i] = set ? src_n[e] : src_p[e];
        d[i] = set ? dst_n[e] : dst_p[e];
    }

    float dgs[4], dgd[4];
    #pragma unroll
    for (int i = 0; i < 4; i++) {
        dgs[i] = g_deg[st[i]][0][s[i]];
        dgd[i] = g_deg[st[i]][1][d[i]];
    }

    float4 v[4];
    #pragma unroll
    for (int i = 0; i < 4; i++) v[i] = Yv[(size_t)s[i] * (D / 4) + lane];

    float c[4];
    #pragma unroll
    for (int i = 0; i < 4; i++) {
        float ns = (dgs[i] > 0.0f) ? rsqrtf(dgs[i]) : 0.0f;
        float nd = (dgd[i] > 0.0f) ? rsqrtf(dgd[i]) : 0.0f;
        c[i] = ns * nd;
    }

    #pragma unroll
    for (int i = 0; i < 4; i++) {
        if (i >= n) break;
        float4 t = v[i];
        t.x *= c[i]; t.y *= c[i]; t.z *= c[i]; t.w *= c[i];
        float* a = &out[((size_t)st[i] * N_NODES + (size_t)d[i]) * D + lane * 4];
        asm volatile("red.global.add.v4.f32 [%0], {%1, %2, %3, %4};"
                     :: "l"(a), "f"(t.x), "f"(t.y), "f"(t.z), "f"(t.w) : "memory");
    }
}

// ---------------- epilogue: out = prelu(out + b) in-place (norms already folded) ----------------
__global__ void epilogue_kernel(float* __restrict__ out, const float* __restrict__ b,
                                const float* __restrict__ prelu_a) {
    size_t idx = (size_t)blockIdx.x * blockDim.x + threadIdx.x;  // float4 index
    size_t total = 2ull * N_NODES * (D / 4);
    if (idx >= total) return;

    int c4 = (int)(idx & 31);
    float pa = prelu_a[0];

    float4 v = reinterpret_cast<float4*>(out)[idx];
    float4 bb = reinterpret_cast<const float4*>(b)[c4];

    float h0 = v.x + bb.x;
    float h1 = v.y + bb.y;
    float h2 = v.z + bb.z;
    float h3 = v.w + bb.w;
    v.x = (h0 > 0.f) ? h0 : pa * h0;
    v.y = (h1 > 0.f) ? h1 : pa * h1;
    v.z = (h2 > 0.f) ? h2 : pa * h2;
    v.w = (h3 > 0.f) ? h3 : pa * h3;
    reinterpret_cast<float4*>(out)[idx] = v;
}

extern "C" void kernel_launch(void* const* d_in, const int* in_sizes, int n_in,
                              void* d_out, int out_size) {
    const float* feats   = (const float*)d_in[0];
    const float* W       = (const float*)d_in[1];
    const float* b       = (const float*)d_in[2];
    const float* prelu_a = (const float*)d_in[3];
    const int* src_pos   = (const int*)d_in[4];
    const int* dst_pos   = (const int*)d_in[5];
    const int* src_neg   = (const int*)d_in[6];
    const int* dst_neg   = (const int*)d_in[7];
    int E = in_sizes[4];
    float* out = (float*)d_out;

    void* deg_ptr = nullptr;
    cudaGetSymbolAddress(&deg_ptr, g_deg);
    cudaMemsetAsync(deg_ptr, 0, sizeof(float) * 2 * 2 * N_NODES);
    cudaMemsetAsync(out, 0, sizeof(float) * 2ull * N_NODES * D);

    degree_kernel<<<(E + 255) / 256, 256>>>(src_pos, dst_pos, src_neg, dst_neg, E);

    int smem = 2 * D * D * sizeof(float);
    cudaFuncSetAttribute(ygemm_kernel, cudaFuncAttributeMaxDynamicSharedMemorySize, smem);
    ygemm_kernel<<<(N_NODES + D - 1) / D, 256, smem>>>(feats, W);

    // merged scatter: one warp per 4 global edges over both sets
    int warps = (2 * E + 3) / 4;
    int sblocks = (warps + 7) / 8;
    scatter2_kernel<<<sblocks, 256>>>(src_pos, dst_pos, src_neg, dst_neg, E, out);

    size_t etotal = 2ull * N_NODES * (D / 4);
    epilogue_kernel<<<(int)((etotal + 255) / 256), 256>>>(out, b, prelu_a);
}

// round 8
// speedup vs baseline: 1.0562x; 1.0562x over previous
#include <cuda_runtime.h>
#include <math.h>

#define N_NODES 100000
#define D 128

// Scratch: degrees [set][0=out(src)/1=in(dst)][node], Y = feats @ W  [N,128]
__device__ float g_deg[2][2][N_NODES];
__device__ float g_y[(size_t)N_NODES * D];

// ---------------- degree histograms (both sets) ----------------
__global__ void degree_kernel(const int* __restrict__ sp, const int* __restrict__ dp,
                              const int* __restrict__ sn, const int* __restrict__ dn, int E) {
    int i = blockIdx.x * blockDim.x + threadIdx.x;
    if (i >= E) return;
    atomicAdd(&g_deg[0][0][sp[i]], 1.0f);
    atomicAdd(&g_deg[0][1][dp[i]], 1.0f);
    atomicAdd(&g_deg[1][0][sn[i]], 1.0f);
    atomicAdd(&g_deg[1][1][dn[i]], 1.0f);
}

// ---------------- Y = feats @ W  (128x128 fp32 GEMM, 128-row tiles) ----------------
__global__ void ygemm_kernel(const float* __restrict__ feats, const float* __restrict__ W) {
    extern __shared__ float sm[];
    float* Ws = sm;            // [k][n]
    float* As = sm + D * D;    // [row][k]

    int tid = threadIdx.x;
    int row0 = blockIdx.x * D;

    {
        const float4* Wv = reinterpret_cast<const float4*>(W);
        float4* Wsv = reinterpret_cast<float4*>(Ws);
        #pragma unroll
        for (int i = tid; i < D * D / 4; i += 256) Wsv[i] = Wv[i];
    }
    {
        const float4* Av = reinterpret_cast<const float4*>(feats);
        float4* Asv = reinterpret_cast<float4*>(As);
        #pragma unroll
        for (int idx = tid; idx < D * (D / 4); idx += 256) {
            int row = idx >> 5;
            int c4  = idx & 31;
            int grow = row0 + row;
            float4 v = make_float4(0.f, 0.f, 0.f, 0.f);
            if (grow < N_NODES) v = Av[(size_t)grow * (D / 4) + c4];
            Asv[idx] = v;
        }
    }
    __syncthreads();

    int ty = tid >> 4;
    int tx = tid & 15;

    float acc[8][8];
    #pragma unroll
    for (int i = 0; i < 8; i++)
        #pragma unroll
        for (int j = 0; j < 8; j++) acc[i][j] = 0.0f;

    #pragma unroll 4
    for (int k = 0; k < D; k++) {
        float a[8];
        #pragma unroll
        for (int i = 0; i < 8; i++) a[i] = As[(ty * 8 + i) * D + k];
        float4 b0 = *reinterpret_cast<const float4*>(&Ws[k * D + tx * 8]);
        float4 b1 = *reinterpret_cast<const float4*>(&Ws[k * D + tx * 8 + 4]);
        float bb[8] = {b0.x, b0.y, b0.z, b0.w, b1.x, b1.y, b1.z, b1.w};
        #pragma unroll
        for (int i = 0; i < 8; i++)
            #pragma unroll
            for (int j = 0; j < 8; j++)
                acc[i][j] = fmaf(a[i], bb[j], acc[i][j]);
    }

    #pragma unroll
    for (int i = 0; i < 8; i++) {
        int grow = row0 + ty * 8 + i;
        if (grow >= N_NODES) continue;
        float4* o = reinterpret_cast<float4*>(&g_y[(size_t)grow * D + tx * 8]);
        o[0] = make_float4(acc[i][0], acc[i][1], acc[i][2], acc[i][3]);
        o[1] = make_float4(acc[i][4], acc[i][5], acc[i][6], acc[i][7]);
    }
}

// ---------------- edge scatter: out[dst] += Y[src] * ns[src] * nd[dst] ----------------
// 4 edges per warp; all gathers issued before any RED (MLP depth 4).
__global__ void scatter_kernel(const int* __restrict__ src, const int* __restrict__ dst,
                               int E, float* __restrict__ outset, int set) {
    int w = (blockIdx.x * blockDim.x + threadIdx.x) >> 5;
    int lane = threadIdx.x & 31;
    int e0 = w * 4;
    if (e0 >= E) return;
    int n = E - e0; if (n > 4) n = 4;

    const float4* Yv = reinterpret_cast<const float4*>(&g_y[0]);

    int s[4], d[4];
    #pragma unroll
    for (int i = 0; i < 4; i++) {
        int e = e0 + ((i < n) ? i : 0);
        s[i] = src[e];
        d[i] = dst[e];
    }
    float dgs[4], dgd[4];
    #pragma unroll
    for (int i = 0; i < 4; i++) {
        dgs[i] = g_deg[set][0][s[i]];
        dgd[i] = g_deg[set][1][d[i]];
    }
    float4 v[4];
    #pragma unroll
    for (int i = 0; i < 4; i++) v[i] = Yv[(size_t)s[i] * (D / 4) + lane];

    float c[4];
    #pragma unroll
    for (int i = 0; i < 4; i++) {
        float ns = (dgs[i] > 0.0f) ? rsqrtf(dgs[i]) : 0.0f;
        float nd = (dgd[i] > 0.0f) ? rsqrtf(dgd[i]) : 0.0f;
        c[i] = ns * nd;
    }
    #pragma unroll
    for (int i = 0; i < 4; i++) {
        if (i >= n) break;
        float4 t = v[i];
        t.x *= c[i]; t.y *= c[i]; t.z *= c[i]; t.w *= c[i];
        float* a = &outset[(size_t)d[i] * D + lane * 4];
        asm volatile("red.global.add.v4.f32 [%0], {%1, %2, %3, %4};"
                     :: "l"(a), "f"(t.x), "f"(t.y), "f"(t.z), "f"(t.w) : "memory");
    }
}

// ---------------- epilogue: out = prelu(out + b) in-place (norms folded in scatter) ----------------
__global__ void epilogue_kernel(float* __restrict__ out, const float* __restrict__ b,
                                const float* __restrict__ prelu_a) {
    size_t idx = (size_t)blockIdx.x * blockDim.x + threadIdx.x;
    size_t total = 2ull * N_NODES * (D / 4);
    if (idx >= total) return;

    int c4 = (int)(idx & 31);
    float pa = prelu_a[0];

    float4 v = reinterpret_cast<float4*>(out)[idx];
    float4 bb = reinterpret_cast<const float4*>(b)[c4];

    float h0 = v.x + bb.x;
    float h1 = v.y + bb.y;
    float h2 = v.z + bb.z;
    float h3 = v.w + bb.w;
    v.x = (h0 > 0.f) ? h0 : pa * h0;
    v.y = (h1 > 0.f) ? h1 : pa * h1;
    v.z = (h2 > 0.f) ? h2 : pa * h2;
    v.w = (h3 > 0.f) ? h3 : pa * h3;
    reinterpret_cast<float4*>(out)[idx] = v;
}

// Lazily-created side stream + events (host objects only; created once at the
// uncaptured correctness call, reused identically in every capture).
static cudaStream_t side_stream() {
    static cudaStream_t s = [] { cudaStream_t t; cudaStreamCreate(&t); return t; }();
    return s;
}
static cudaEvent_t ev_fork() {
    static cudaEvent_t e = [] { cudaEvent_t t; cudaEventCreateWithFlags(&t, cudaEventDisableTiming); return t; }();
    return e;
}
static cudaEvent_t ev_join() {
    static cudaEvent_t e = [] { cudaEvent_t t; cudaEventCreateWithFlags(&t, cudaEventDisableTiming); return t; }();
    return e;
}

extern "C" void kernel_launch(void* const* d_in, const int* in_sizes, int n_in,
                              void* d_out, int out_size) {
    const float* feats   = (const float*)d_in[0];
    const float* W       = (const float*)d_in[1];
    const float* b       = (const float*)d_in[2];
    const float* prelu_a = (const float*)d_in[3];
    const int* src_pos   = (const int*)d_in[4];
    const int* dst_pos   = (const int*)d_in[5];
    const int* src_neg   = (const int*)d_in[6];
    const int* dst_neg   = (const int*)d_in[7];
    int E = in_sizes[4];
    float* out = (float*)d_out;

    cudaStream_t s2 = side_stream();
    cudaEvent_t e1 = ev_fork();
    cudaEvent_t e2 = ev_join();

    void* deg_ptr = nullptr;
    cudaGetSymbolAddress(&deg_ptr, g_deg);

    // Fork: side stream does prologue (memsets + degree) while legacy stream runs ygemm.
    cudaEventRecord(e1, 0);
    cudaStreamWaitEvent(s2, e1, 0);

    cudaMemsetAsync(deg_ptr, 0, sizeof(float) * 2 * 2 * N_NODES, s2);
    cudaMemsetAsync(out, 0, sizeof(float) * 2ull * N_NODES * D, s2);
    degree_kernel<<<(E + 255) / 256, 256, 0, s2>>>(src_pos, dst_pos, src_neg, dst_neg, E);
    cudaEventRecord(e2, s2);

    // Legacy stream: the long FMA-bound GEMM (independent of prologue).
    int smem = 2 * D * D * sizeof(float);
    cudaFuncSetAttribute(ygemm_kernel, cudaFuncAttributeMaxDynamicSharedMemorySize, smem);
    ygemm_kernel<<<(N_NODES + D - 1) / D, 256, smem>>>(feats, W);

    // Join, then scatter + epilogue on legacy stream.
    cudaStreamWaitEvent(0, e2, 0);

    int warps = (E + 3) / 4;
    int sblocks = (warps + 7) / 8;
    float* out_pos = out;
    float* out_neg = out + (size_t)N_NODES * D;
    scatter_kernel<<<sblocks, 256>>>(src_pos, dst_pos, E, out_pos, 0);
    scatter_kernel<<<sblocks, 256>>>(src_neg, dst_neg, E, out_neg, 1);

    size_t etotal = 2ull * N_NODES * (D / 4);
    epilogue_kernel<<<(int)((etotal + 255) / 256), 256>>>(out, b, prelu_a);
}

// round 9
// speedup vs baseline: 1.4123x; 1.3371x over previous
#include <cuda_runtime.h>
#include <math.h>

#define N_NODES 100000
#define D 128
#define EMAX 800000

// Scratch: degrees [set][0=out(src)/1=in(dst)][node], Y = feats@W, CSR-by-dst
__device__ float g_deg[2][2][N_NODES];
__device__ float g_y[(size_t)N_NODES * D];
__device__ int g_base[2][N_NODES];
__device__ int g_cursor[2][N_NODES];
__device__ int g_csr[2][EMAX];
__device__ int g_counter[2];

// ---------------- degree histograms (both sets) ----------------
__global__ void degree_kernel(const int* __restrict__ sp, const int* __restrict__ dp,
                              const int* __restrict__ sn, const int* __restrict__ dn, int E) {
    int i = blockIdx.x * blockDim.x + threadIdx.x;
    if (i >= E) return;
    atomicAdd(&g_deg[0][0][sp[i]], 1.0f);
    atomicAdd(&g_deg[0][1][dp[i]], 1.0f);
    atomicAdd(&g_deg[1][0][sn[i]], 1.0f);
    atomicAdd(&g_deg[1][1][dn[i]], 1.0f);
}

// ---------------- CSR base assignment: block scan + one atomic per block ----------------
__global__ void base_kernel() {
    int set = blockIdx.y;
    int tid = threadIdx.x;
    int v = blockIdx.x * 256 + tid;
    int d = (v < N_NODES) ? (int)g_deg[set][1][v] : 0;

    __shared__ int sh[256];
    sh[tid] = d;
    __syncthreads();
    #pragma unroll
    for (int off = 1; off < 256; off <<= 1) {
        int t = (tid >= off) ? sh[tid - off] : 0;
        __syncthreads();
        sh[tid] += t;
        __syncthreads();
    }
    int excl = sh[tid] - d;

    __shared__ int blockBase;
    if (tid == 255) blockBase = atomicAdd(&g_counter[set], sh[255]);
    __syncthreads();

    if (v < N_NODES) {
        int b = blockBase + excl;
        g_base[set][v] = b;
        g_cursor[set][v] = b;
    }
}

// ---------------- CSR fill: bucket edges by dst ----------------
__global__ void fill_kernel(const int* __restrict__ sp, const int* __restrict__ dp,
                            const int* __restrict__ sn, const int* __restrict__ dn, int E) {
    int i = blockIdx.x * blockDim.x + threadIdx.x;
    if (i >= E) return;
    int p = atomicAdd(&g_cursor[0][dp[i]], 1);
    g_csr[0][p] = sp[i];
    int q = atomicAdd(&g_cursor[1][dn[i]], 1);
    g_csr[1][q] = sn[i];
}

// ---------------- Y = feats @ W  (128x128 fp32 GEMM, 128-row tiles) ----------------
__global__ void ygemm_kernel(const float* __restrict__ feats, const float* __restrict__ W) {
    extern __shared__ float sm[];
    float* Ws = sm;            // [k][n]
    float* As = sm + D * D;    // [row][k]

    int tid = threadIdx.x;
    int row0 = blockIdx.x * D;

    {
        const float4* Wv = reinterpret_cast<const float4*>(W);
        float4* Wsv = reinterpret_cast<float4*>(Ws);
        #pragma unroll
        for (int i = tid; i < D * D / 4; i += 256) Wsv[i] = Wv[i];
    }
    {
        const float4* Av = reinterpret_cast<const float4*>(feats);
        float4* Asv = reinterpret_cast<float4*>(As);
        #pragma unroll
        for (int idx = tid; idx < D * (D / 4); idx += 256) {
            int row = idx >> 5;
            int c4  = idx & 31;
            int grow = row0 + row;
            float4 v = make_float4(0.f, 0.f, 0.f, 0.f);
            if (grow < N_NODES) v = Av[(size_t)grow * (D / 4) + c4];
            Asv[idx] = v;
        }
    }
    __syncthreads();

    int ty = tid >> 4;
    int tx = tid & 15;

    float acc[8][8];
    #pragma unroll
    for (int i = 0; i < 8; i++)
        #pragma unroll
        for (int j = 0; j < 8; j++) acc[i][j] = 0.0f;

    #pragma unroll 4
    for (int k = 0; k < D; k++) {
        float a[8];
        #pragma unroll
        for (int i = 0; i < 8; i++) a[i] = As[(ty * 8 + i) * D + k];
        float4 b0 = *reinterpret_cast<const float4*>(&Ws[k * D + tx * 8]);
        float4 b1 = *reinterpret_cast<const float4*>(&Ws[k * D + tx * 8 + 4]);
        float bb[8] = {b0.x, b0.y, b0.z, b0.w, b1.x, b1.y, b1.z, b1.w};
        #pragma unroll
        for (int i = 0; i < 8; i++)
            #pragma unroll
            for (int j = 0; j < 8; j++)
                acc[i][j] = fmaf(a[i], bb[j], acc[i][j]);
    }

    #pragma unroll
    for (int i = 0; i < 8; i++) {
        int grow = row0 + ty * 8 + i;
        if (grow >= N_NODES) continue;
        float4* o = reinterpret_cast<float4*>(&g_y[(size_t)grow * D + tx * 8]);
        o[0] = make_float4(acc[i][0], acc[i][1], acc[i][2], acc[i][3]);
        o[1] = make_float4(acc[i][4], acc[i][5], acc[i][6], acc[i][7]);
    }
}

// ---------------- CSR gather: out[v] = prelu(nd * sum_e Y[src_e]*ns[src_e] + b) ----------------
// One warp per (set, node); lane handles 4 consecutive floats. No atomics, fused epilogue.
__global__ void gather_kernel(float* __restrict__ out, const float* __restrict__ b,
                              const float* __restrict__ prelu_a) {
    int gw = (blockIdx.x * blockDim.x + threadIdx.x) >> 5;
    int lane = threadIdx.x & 31;
    if (gw >= 2 * N_NODES) return;
    int set = (gw >= N_NODES) ? 1 : 0;
    int v = gw - set * N_NODES;

    int cnt = (int)g_deg[set][1][v];
    int base = g_base[set][v];
    const int* csr = &g_csr[set][0];
    const float* deg_out = &g_deg[set][0][0];
    const float4* Yv = reinterpret_cast<const float4*>(&g_y[0]);

    float ax = 0.f, ay = 0.f, az = 0.f, aw = 0.f;

    int i = 0;
    for (; i + 4 <= cnt; i += 4) {
        int s0 = csr[base + i], s1 = csr[base + i + 1];
        int s2 = csr[base + i + 2], s3 = csr[base + i + 3];
        float d0 = deg_out[s0], d1 = deg_out[s1], d2 = deg_out[s2], d3 = deg_out[s3];
        float4 v0 = Yv[(size_t)s0 * (D / 4) + lane];
        float4 v1 = Yv[(size_t)s1 * (D / 4) + lane];
        float4 v2 = Yv[(size_t)s2 * (D / 4) + lane];
        float4 v3 = Yv[(size_t)s3 * (D / 4) + lane];
        float n0 = rsqrtf(d0), n1 = rsqrtf(d1), n2 = rsqrtf(d2), n3 = rsqrtf(d3);
        ax += v0.x * n0 + v1.x * n1 + v2.x * n2 + v3.x * n3;
        ay += v0.y * n0 + v1.y * n1 + v2.y * n2 + v3.y * n3;
        az += v0.z * n0 + v1.z * n1 + v2.z * n2 + v3.z * n3;
        aw += v0.w * n0 + v1.w * n1 + v2.w * n2 + v3.w * n3;
    }
    for (; i < cnt; i++) {
        int s = csr[base + i];
        float d = deg_out[s];
        float4 vv = Yv[(size_t)s * (D / 4) + lane];
        float n = rsqrtf(d);
        ax += vv.x * n; ay += vv.y * n; az += vv.z * n; aw += vv.w * n;
    }

    float nd = (cnt > 0) ? rsqrtf((float)cnt) : 0.0f;
    float pa = prelu_a[0];
    float4 bb = reinterpret_cast<const float4*>(b)[lane];

    float h0 = ax * nd + bb.x;
    float h1 = ay * nd + bb.y;
    float h2 = az * nd + bb.z;
    float h3 = aw * nd + bb.w;
    float4 r;
    r.x = (h0 > 0.f) ? h0 : pa * h0;
    r.y = (h1 > 0.f) ? h1 : pa * h1;
    r.z = (h2 > 0.f) ? h2 : pa * h2;
    r.w = (h3 > 0.f) ? h3 : pa * h3;
    reinterpret_cast<float4*>(out)[((size_t)set * N_NODES + v) * (D / 4) + lane] = r;
}

// Lazily-created side stream + events (host objects only).
static cudaStream_t side_stream() {
    static cudaStream_t s = [] { cudaStream_t t; cudaStreamCreate(&t); return t; }();
    return s;
}
static cudaEvent_t ev_fork() {
    static cudaEvent_t e = [] { cudaEvent_t t; cudaEventCreateWithFlags(&t, cudaEventDisableTiming); return t; }();
    return e;
}
static cudaEvent_t ev_join() {
    static cudaEvent_t e = [] { cudaEvent_t t; cudaEventCreateWithFlags(&t, cudaEventDisableTiming); return t; }();
    return e;
}

extern "C" void kernel_launch(void* const* d_in, const int* in_sizes, int n_in,
                              void* d_out, int out_size) {
    const float* feats   = (const float*)d_in[0];
    const float* W       = (const float*)d_in[1];
    const float* b       = (const float*)d_in[2];
    const float* prelu_a = (const float*)d_in[3];
    const int* src_pos   = (const int*)d_in[4];
    const int* dst_pos   = (const int*)d_in[5];
    const int* src_neg   = (const int*)d_in[6];
    const int* dst_neg   = (const int*)d_in[7];
    int E = in_sizes[4];
    float* out = (float*)d_out;

    cudaStream_t s2 = side_stream();
    cudaEvent_t e1 = ev_fork();
    cudaEvent_t e2 = ev_join();

    void* deg_ptr = nullptr;
    void* cnt_ptr = nullptr;
    cudaGetSymbolAddress(&deg_ptr, g_deg);
    cudaGetSymbolAddress(&cnt_ptr, g_counter);

    // Fork: side stream builds degrees + CSR while legacy stream runs ygemm.
    cudaEventRecord(e1, 0);
    cudaStreamWaitEvent(s2, e1, 0);

    cudaMemsetAsync(deg_ptr, 0, sizeof(float) * 2 * 2 * N_NODES, s2);
    cudaMemsetAsync(cnt_ptr, 0, sizeof(int) * 2, s2);
    degree_kernel<<<(E + 255) / 256, 256, 0, s2>>>(src_pos, dst_pos, src_neg, dst_neg, E);
    {
        dim3 grid((N_NODES + 255) / 256, 2);
        base_kernel<<<grid, 256, 0, s2>>>();
    }
    fill_kernel<<<(E + 255) / 256, 256, 0, s2>>>(src_pos, dst_pos, src_neg, dst_neg, E);
    cudaEventRecord(e2, s2);

    // Legacy stream: the long FMA-bound GEMM (independent of CSR build).
    int smem = 2 * D * D * sizeof(float);
    cudaFuncSetAttribute(ygemm_kernel, cudaFuncAttributeMaxDynamicSharedMemorySize, smem);
    ygemm_kernel<<<(N_NODES + D - 1) / D, 256, smem>>>(feats, W);

    // Join, then fused gather (aggregation + norm + bias + PReLU).
    cudaStreamWaitEvent(0, e2, 0);

    int gwarps = 2 * N_NODES;
    int gblocks = (gwarps + 7) / 8;   // 8 warps per 256-thread block
    gather_kernel<<<gblocks, 256>>>(out, b, prelu_a);
}